// round 9
// baseline (speedup 1.0000x reference)
#include <cuda_runtime.h>
#include <cuda_bf16.h>
#include <cstdint>
#include <math.h>

// ============================================================================
// NTXentLoss (B=8192, D=1024) — pipelined mma.sync bf16 GEMM (sm_103 baseline
// ISA; tcgen05 rejected by this harness's ptxas target), single sweep
// producing row (i2s) and column (s2i) softmax stats.
// ============================================================================

#define NB 8192
#define ND 1024
#define NT 64              // 64 tiles per dimension (128x128 tiles)
#define TEMP_INV 20.0f
#define HNW 1.5f
#define STG 32768          // bytes per pipeline stage (A 16K + B 16K)
#define OFFB 16384
#define SMEM_TOT 98304     // 3 stages
#define SW128(o) ((o) ^ (((o) >> 3) & 0x70))

__device__ __nv_bfloat16 g_a[(size_t)NB * ND];   // image * 20
__device__ __nv_bfloat16 g_b[(size_t)NB * ND];   // song
__device__ float g_rm[(size_t)NT * NB], g_rs[(size_t)NT * NB],
                 g_rv[(size_t)NT * NB], g_rd[(size_t)NT * NB];   // [jt][row]
__device__ float g_cm[(size_t)NT * NB], g_cs[(size_t)NT * NB],
                 g_cv[(size_t)NT * NB], g_cd[(size_t)NT * NB];   // [it][col]
__device__ double g_acc[2];

// ----------------------------------------------------------------------------
__global__ void convert_kernel(const float* __restrict__ img,
                               const float* __restrict__ song) {
    size_t i = (size_t)blockIdx.x * blockDim.x + threadIdx.x;
    if (i == 0) { g_acc[0] = 0.0; g_acc[1] = 0.0; }
    size_t idx = i * 4;
    if (idx < (size_t)NB * ND) {
        float4 a = *(const float4*)(img + idx);
        float4 b = *(const float4*)(song + idx);
        *(__nv_bfloat162*)(g_a + idx)     = __floats2bfloat162_rn(a.x * TEMP_INV, a.y * TEMP_INV);
        *(__nv_bfloat162*)(g_a + idx + 2) = __floats2bfloat162_rn(a.z * TEMP_INV, a.w * TEMP_INV);
        *(__nv_bfloat162*)(g_b + idx)     = __floats2bfloat162_rn(b.x, b.y);
        *(__nv_bfloat162*)(g_b + idx + 2) = __floats2bfloat162_rn(b.z, b.w);
    }
}

// issue one 64-wide K chunk: A 128x64 bf16 (16KB) + B 128x64 bf16 (16KB),
// SW128-swizzled 128-byte rows => 2048 x 16B cp.async transfers total.
#define ISSUE_CHUNK(kc_) do { \
    uint32_t sb = su + (uint32_t)(((kc_) % 3) * STG); \
    const __nv_bfloat16* Ab = g_a + (size_t)i0 * ND + (kc_) * 64; \
    const __nv_bfloat16* Bb = g_b + (size_t)j0 * ND + (kc_) * 64; \
    for (int c = tid; c < 2048; c += 256) { \
        int hb = c >> 10, idx = c & 1023; \
        int row = idx >> 3, k16 = idx & 7; \
        const __nv_bfloat16* src = (hb ? Bb : Ab) + (size_t)row * ND + k16 * 8; \
        uint32_t dst = sb + (hb ? OFFB : 0) + SW128((uint32_t)(row * 128 + k16 * 16)); \
        asm volatile("cp.async.cg.shared.global [%0], [%1], 16;\n" ::"r"(dst), "l"(src)); \
    } \
    asm volatile("cp.async.commit_group;\n" ::: "memory"); \
} while (0)

__global__ __launch_bounds__(256, 1) void gemm_stats_kernel() {
    extern __shared__ __align__(1024) char smem[];
    const uint32_t su = (uint32_t)__cvta_generic_to_shared(smem);
    const int tid = threadIdx.x, lane = tid & 31, w = tid >> 5;
    const int wn = w & 1;          // n-half (64 cols)
    const int wm = w >> 1;         // m-quarter (32 rows)
    const int it = blockIdx.x & 63, jt = blockIdx.x >> 6;
    const int i0 = it * 128, j0 = jt * 128;
    const int mat = lane >> 3;

    ISSUE_CHUNK(0); ISSUE_CHUNK(1);

    float ac[2][8][4];
    #pragma unroll
    for (int a = 0; a < 2; a++)
        #pragma unroll
        for (int b = 0; b < 8; b++)
            #pragma unroll
            for (int e = 0; e < 4; e++) ac[a][b][e] = 0.f;

    for (int kc = 0; kc < 16; ++kc) {
        if (kc < 15) asm volatile("cp.async.wait_group 1;\n" ::: "memory");
        else         asm volatile("cp.async.wait_group 0;\n" ::: "memory");
        __syncthreads();
        if (kc + 2 < 16) ISSUE_CHUNK(kc + 2);

        uint32_t sA = su + (uint32_t)((kc % 3) * STG);
        uint32_t sB = sA + OFFB;
        #pragma unroll
        for (int ks = 0; ks < 4; ++ks) {
            uint32_t af[2][4];
            #pragma unroll
            for (int mf = 0; mf < 2; ++mf) {
                int row = wm * 32 + mf * 16 + ((mat & 1) << 3) + (lane & 7);
                uint32_t addr = sA + SW128((uint32_t)(row * 128 + ks * 32 + ((mat >> 1) << 4)));
                asm volatile(
                    "ldmatrix.sync.aligned.m8n8.x4.shared.b16 {%0,%1,%2,%3}, [%4];\n"
                    : "=r"(af[mf][0]), "=r"(af[mf][1]), "=r"(af[mf][2]), "=r"(af[mf][3])
                    : "r"(addr));
            }
            uint32_t bfr[8][2];
            #pragma unroll
            for (int P = 0; P < 4; ++P) {
                int nrow = wn * 64 + P * 16 + ((mat >> 1) << 3) + (lane & 7);
                uint32_t addr = sB + SW128((uint32_t)(nrow * 128 + ks * 32 + ((mat & 1) << 4)));
                asm volatile(
                    "ldmatrix.sync.aligned.m8n8.x4.shared.b16 {%0,%1,%2,%3}, [%4];\n"
                    : "=r"(bfr[2 * P][0]), "=r"(bfr[2 * P][1]),
                      "=r"(bfr[2 * P + 1][0]), "=r"(bfr[2 * P + 1][1])
                    : "r"(addr));
            }
            #pragma unroll
            for (int mf = 0; mf < 2; ++mf)
                #pragma unroll
                for (int nf = 0; nf < 8; ++nf) {
                    asm volatile(
                        "mma.sync.aligned.m16n8k16.row.col.f32.bf16.bf16.f32 "
                        "{%0,%1,%2,%3},{%4,%5,%6,%7},{%8,%9},{%0,%1,%2,%3};\n"
                        : "+f"(ac[mf][nf][0]), "+f"(ac[mf][nf][1]),
                          "+f"(ac[mf][nf][2]), "+f"(ac[mf][nf][3])
                        : "r"(af[mf][0]), "r"(af[mf][1]), "r"(af[mf][2]), "r"(af[mf][3]),
                          "r"(bfr[nf][0]), "r"(bfr[nf][1]));
                }
        }
    }
    __syncthreads();   // stage smem now reusable as epilogue scratch

    float* sp  = (float*)smem;
    float* pm  = sp;          // [2 wn][128 rows]
    float* ps  = sp + 256;
    float* pv  = sp + 512;
    float* pd  = sp + 768;
    float* cmS = sp + 1024;   // [4 wm][128 cols]
    float* csS = sp + 1536;
    float* cvS = sp + 2048;
    float* cdS = sp + 2560;

    // --- row stats: per thread 4 rows x 16 cols; reduce over 4-lane group ---
    #pragma unroll
    for (int mf = 0; mf < 2; ++mf) {
        #pragma unroll
        for (int q = 0; q < 2; ++q) {
            int rowl = wm * 32 + mf * 16 + q * 8 + (lane >> 2);
            int grow = i0 + rowl;
            float lm = -INFINITY, lv = -INFINITY, ld = -INFINITY;
            #pragma unroll
            for (int nf = 0; nf < 8; ++nf)
                #pragma unroll
                for (int e = 0; e < 2; ++e) {
                    float x = ac[mf][nf][q * 2 + e];
                    int gcol = j0 + wn * 64 + nf * 8 + ((lane & 3) << 1) + e;
                    lm = fmaxf(lm, x);
                    if (gcol == grow) ld = x; else lv = fmaxf(lv, x);
                }
            #pragma unroll
            for (int o = 1; o < 4; o <<= 1) {
                lm = fmaxf(lm, __shfl_xor_sync(0xffffffffu, lm, o));
                lv = fmaxf(lv, __shfl_xor_sync(0xffffffffu, lv, o));
                ld = fmaxf(ld, __shfl_xor_sync(0xffffffffu, ld, o));
            }
            float ls = 0.f;
            #pragma unroll
            for (int nf = 0; nf < 8; ++nf)
                #pragma unroll
                for (int e = 0; e < 2; ++e)
                    ls += __expf(ac[mf][nf][q * 2 + e] - lm);
            #pragma unroll
            for (int o = 1; o < 4; o <<= 1)
                ls += __shfl_xor_sync(0xffffffffu, ls, o);
            if ((lane & 3) == 0) {
                pm[wn * 128 + rowl] = lm;
                ps[wn * 128 + rowl] = ls;
                pv[wn * 128 + rowl] = lv;
                pd[wn * 128 + rowl] = ld;
            }
        }
    }
    // --- col stats: per thread 16 cols x 4 rows; reduce over 8 lanes ---
    #pragma unroll
    for (int nf = 0; nf < 8; ++nf) {
        #pragma unroll
        for (int e = 0; e < 2; ++e) {
            int coll = wn * 64 + nf * 8 + ((lane & 3) << 1) + e;
            int gcol = j0 + coll;
            float cm = -INFINITY, cv = -INFINITY, cd = -INFINITY;
            #pragma unroll
            for (int mf = 0; mf < 2; ++mf)
                #pragma unroll
                for (int q = 0; q < 2; ++q) {
                    float x = ac[mf][nf][q * 2 + e];
                    int grow = i0 + wm * 32 + mf * 16 + q * 8 + (lane >> 2);
                    cm = fmaxf(cm, x);
                    if (grow == gcol) cd = x; else cv = fmaxf(cv, x);
                }
            #pragma unroll
            for (int o = 4; o < 32; o <<= 1) {
                cm = fmaxf(cm, __shfl_xor_sync(0xffffffffu, cm, o));
                cv = fmaxf(cv, __shfl_xor_sync(0xffffffffu, cv, o));
                cd = fmaxf(cd, __shfl_xor_sync(0xffffffffu, cd, o));
            }
            float cs = 0.f;
            #pragma unroll
            for (int mf = 0; mf < 2; ++mf)
                #pragma unroll
                for (int q = 0; q < 2; ++q)
                    cs += __expf(ac[mf][nf][q * 2 + e] - cm);
            #pragma unroll
            for (int o = 4; o < 32; o <<= 1)
                cs += __shfl_xor_sync(0xffffffffu, cs, o);
            if (lane < 4) {
                cmS[wm * 128 + coll] = cm; csS[wm * 128 + coll] = cs;
                cvS[wm * 128 + coll] = cv; cdS[wm * 128 + coll] = cd;
            }
        }
    }
    __syncthreads();

    if (tid < 128) {
        // rows: merge 2 wn halves, write per-tile partials
        {
            float m = pm[tid], s = ps[tid], v = pv[tid], d = pd[tid];
            float lm = pm[128 + tid], ls = ps[128 + tid];
            float nm = fmaxf(m, lm);
            s = s * __expf(m - nm) + ls * __expf(lm - nm);
            m = nm;
            v = fmaxf(v, pv[128 + tid]);
            d = fmaxf(d, pd[128 + tid]);
            size_t o = (size_t)jt * NB + i0 + tid;
            g_rm[o] = m; g_rs[o] = s; g_rv[o] = v; g_rd[o] = d;
        }
        // cols: merge 4 wm quarters
        {
            float m = cmS[tid], s = csS[tid], v = cvS[tid], d = cdS[tid];
            #pragma unroll
            for (int h = 1; h < 4; ++h) {
                float lm = cmS[h * 128 + tid], ls = csS[h * 128 + tid];
                float nm = fmaxf(m, lm);
                s = s * __expf(m - nm) + ls * __expf(lm - nm);
                m = nm;
                v = fmaxf(v, cvS[h * 128 + tid]);
                d = fmaxf(d, cdS[h * 128 + tid]);
            }
            size_t o = (size_t)it * NB + j0 + tid;
            g_cm[o] = m; g_cs[o] = s; g_cv[o] = v; g_cd[o] = d;
        }
    }
}

// ----------------------------------------------------------------------------
__device__ __forceinline__ float finish_loss(float m, float s, float v, float d) {
    float hv = HNW * v;
    float M2 = fmaxf(m, hv);
    float S = s * __expf(m - M2) - __expf(v - M2) + __expf(hv - M2);
    return (M2 + logf(S)) - d;
}

__global__ void row_merge_kernel() {
    __shared__ float red[256];
    int r = blockIdx.x * 256 + threadIdx.x;
    float m = -INFINITY, s = 0.f, v = -INFINITY, d = -INFINITY;
    for (int j = 0; j < NT; ++j) {
        size_t o = (size_t)j * NB + r;
        float lm = g_rm[o], ls = g_rs[o];
        float nm = fmaxf(m, lm);
        s = s * __expf(m - nm) + ls * __expf(lm - nm);
        m = nm; v = fmaxf(v, g_rv[o]); d = fmaxf(d, g_rd[o]);
    }
    red[threadIdx.x] = finish_loss(m, s, v, d);
    __syncthreads();
    if (threadIdx.x == 0) {
        float sum = 0.f;
        #pragma unroll 8
        for (int i = 0; i < 256; ++i) sum += red[i];
        atomicAdd(&g_acc[0], (double)sum);
    }
}

__global__ void col_merge_kernel() {
    __shared__ float red[256];
    int c = blockIdx.x * 256 + threadIdx.x;
    float m = -INFINITY, s = 0.f, v = -INFINITY, d = -INFINITY;
    for (int i = 0; i < NT; ++i) {
        size_t o = (size_t)i * NB + c;
        float lm = g_cm[o], ls = g_cs[o];
        float nm = fmaxf(m, lm);
        s = s * __expf(m - nm) + ls * __expf(lm - nm);
        m = nm; v = fmaxf(v, g_cv[o]); d = fmaxf(d, g_cd[o]);
    }
    red[threadIdx.x] = finish_loss(m, s, v, d);
    __syncthreads();
    if (threadIdx.x == 0) {
        float sum = 0.f;
        #pragma unroll 8
        for (int i = 0; i < 256; ++i) sum += red[i];
        atomicAdd(&g_acc[1], (double)sum);
    }
}

__global__ void finalize_kernel(float* out) {
    out[0] = (float)((g_acc[0] + g_acc[1]) * (0.5 / (double)NB));
}

// ----------------------------------------------------------------------------
extern "C" void kernel_launch(void* const* d_in, const int* in_sizes, int n_in,
                              void* d_out, int out_size) {
    const float* img  = (const float*)d_in[0];
    const float* song = (const float*)d_in[1];
    float* out = (float*)d_out;

    cudaFuncSetAttribute(gemm_stats_kernel,
                         cudaFuncAttributeMaxDynamicSharedMemorySize, SMEM_TOT);

    convert_kernel<<<NB * ND / 4 / 256, 256>>>(img, song);
    gemm_stats_kernel<<<NT * NT, 256, SMEM_TOT>>>();
    row_merge_kernel<<<NB / 256, 256>>>();
    col_merge_kernel<<<NB / 256, 256>>>();
    finalize_kernel<<<1, 1>>>(out);
}